// round 4
// baseline (speedup 1.0000x reference)
#include <cuda_runtime.h>
#include <cuda_bf16.h>
#include <cstdint>
#include <math.h>

#define T 2048      // tokens
#define D 1024      // model dim
#define H 2816      // ffn hidden
#define E 8         // experts
#define NPAIR (T*2) // token-expert pairs

#define BM 128
#define BN 64
#define BK 64
#define STRIDE 144  // padded bytes per k-row: 64*2 + 16 (bank-conflict-free)

// ---------------- device globals (no allocation allowed) ----------------
__device__ int   g_pidx[NPAIR];
__device__ float g_pw[NPAIR];
__device__ int   g_count[E];
__device__ int   g_plist[E][T];
__device__ float g_wlist[E][T];

__device__ __align__(16) __nv_bfloat16 g_xh[T*D],  g_xl[T*D];
__device__ __align__(16) __nv_bfloat16 g_hh[(size_t)NPAIR*H], g_hl[(size_t)NPAIR*H];
__device__ float g_yp[(size_t)NPAIR*D];

// ---------------- helpers ----------------
__device__ __forceinline__ uint32_t smem_u32(const void* p) {
    uint32_t a;
    asm("{ .reg .u64 t; cvta.to.shared.u64 t, %1; cvt.u32.u64 %0, t; }" : "=r"(a) : "l"(p));
    return a;
}
__device__ __forceinline__ void cp16(uint32_t dst, const void* src) {
    asm volatile("cp.async.cg.shared.global [%0], [%1], 16;" :: "r"(dst), "l"(src));
}
#define CP_COMMIT() asm volatile("cp.async.commit_group;" ::: "memory")
#define CP_WAIT1()  asm volatile("cp.async.wait_group 1;" ::: "memory")

__device__ __forceinline__ void mma16816(float* c, const uint32_t* a, const uint32_t* b) {
    asm volatile("mma.sync.aligned.m16n8k16.row.col.f32.bf16.bf16.f32 "
        "{%0,%1,%2,%3}, {%4,%5,%6,%7}, {%8,%9}, {%0,%1,%2,%3};"
        : "+f"(c[0]), "+f"(c[1]), "+f"(c[2]), "+f"(c[3])
        : "r"(a[0]), "r"(a[1]), "r"(a[2]), "r"(a[3]), "r"(b[0]), "r"(b[1]));
}
__device__ __forceinline__ void ldA(uint32_t* a, const char* tile, int rm, int kk, int g, int q) {
    const char* p = tile + (rm + g) * STRIDE + (kk + q * 2) * 2;
    a[0] = *(const uint32_t*)p;
    a[1] = *(const uint32_t*)(p + 8 * STRIDE);
    a[2] = *(const uint32_t*)(p + 16);
    a[3] = *(const uint32_t*)(p + 8 * STRIDE + 16);
}
__device__ __forceinline__ void ldB(uint32_t* b, const char* tile, int cn, int kk, int g, int q) {
    const char* p = tile + (cn + g) * STRIDE + (kk + q * 2) * 2;
    b[0] = *(const uint32_t*)p;
    b[1] = *(const uint32_t*)(p + 16);
}
__device__ __forceinline__ uint32_t b2u(__nv_bfloat162 v) { return *reinterpret_cast<uint32_t*>(&v); }

// split a pair of float4 (8 consecutive fp32) into 8 bf16 hi + 8 bf16 lo
__device__ __forceinline__ void cvt_pair(const float4 A, const float4 B, uint4& hi, uint4& lo) {
    __nv_bfloat162 h0 = __floats2bfloat162_rn(A.x, A.y);
    __nv_bfloat162 h1 = __floats2bfloat162_rn(A.z, A.w);
    __nv_bfloat162 h2 = __floats2bfloat162_rn(B.x, B.y);
    __nv_bfloat162 h3 = __floats2bfloat162_rn(B.z, B.w);
    __nv_bfloat162 l0 = __floats2bfloat162_rn(A.x - __bfloat162float(h0.x), A.y - __bfloat162float(h0.y));
    __nv_bfloat162 l1 = __floats2bfloat162_rn(A.z - __bfloat162float(h1.x), A.w - __bfloat162float(h1.y));
    __nv_bfloat162 l2 = __floats2bfloat162_rn(B.x - __bfloat162float(h2.x), B.y - __bfloat162float(h2.y));
    __nv_bfloat162 l3 = __floats2bfloat162_rn(B.z - __bfloat162float(h3.x), B.w - __bfloat162float(h3.y));
    hi = make_uint4(b2u(h0), b2u(h1), b2u(h2), b2u(h3));
    lo = make_uint4(b2u(l0), b2u(l1), b2u(l2), b2u(l3));
}

// ---------------- split fp32 -> bf16 hi/lo (x only; tiny) ----------------
__global__ void split_kernel(const float* __restrict__ src, __nv_bfloat16* __restrict__ hi,
                             __nv_bfloat16* __restrict__ lo, int n4) {
    int i = blockIdx.x * 256 + threadIdx.x;
    if (i >= n4) return;
    float4 v = ((const float4*)src)[i];
    __nv_bfloat162 h0 = __floats2bfloat162_rn(v.x, v.y);
    __nv_bfloat162 h1 = __floats2bfloat162_rn(v.z, v.w);
    __nv_bfloat162 l0 = __floats2bfloat162_rn(v.x - __bfloat162float(h0.x), v.y - __bfloat162float(h0.y));
    __nv_bfloat162 l1 = __floats2bfloat162_rn(v.z - __bfloat162float(h1.x), v.w - __bfloat162float(h1.y));
    ((uint2*)hi)[i] = make_uint2(b2u(h0), b2u(h1));
    ((uint2*)lo)[i] = make_uint2(b2u(l0), b2u(l1));
}

// ---------------- gate / routing ----------------
__global__ void gate_kernel(const float* __restrict__ x, const float* __restrict__ Wg) {
    int t = blockIdx.x;
    int warp = threadIdx.x >> 5, lane = threadIdx.x & 31;
    __shared__ float logits[E];
    const float* xr = x + (size_t)t * D;
    const float* wr = Wg + (size_t)warp * D;
    float s = 0.f;
    #pragma unroll
    for (int j = 0; j < D / 128; j++) {
        int i = lane * 4 + j * 128;
        float4 xv = *(const float4*)(xr + i);
        float4 wv = *(const float4*)(wr + i);
        s += xv.x * wv.x + xv.y * wv.y + xv.z * wv.z + xv.w * wv.w;
    }
    #pragma unroll
    for (int o = 16; o; o >>= 1) s += __shfl_xor_sync(0xffffffffu, s, o);
    if (lane == 0) logits[warp] = s;
    __syncthreads();
    if (threadIdx.x == 0) {
        float m = logits[0];
        #pragma unroll
        for (int e2 = 1; e2 < E; e2++) m = fmaxf(m, logits[e2]);
        float p[E];
        #pragma unroll
        for (int e2 = 0; e2 < E; e2++) p[e2] = expf(logits[e2] - m);
        int i0 = 0;
        #pragma unroll
        for (int e2 = 1; e2 < E; e2++) if (p[e2] > p[i0]) i0 = e2;
        int i1 = (i0 == 0) ? 1 : 0;
        #pragma unroll
        for (int e2 = 0; e2 < E; e2++) if (e2 != i0 && p[e2] > p[i1]) i1 = e2;
        float inv = 1.f / (p[i0] + p[i1]);
        g_pidx[2*t]   = i0; g_pw[2*t]   = p[i0] * inv;
        g_pidx[2*t+1] = i1; g_pw[2*t+1] = p[i1] * inv;
    }
}

__global__ void build_lists_kernel() {
    int e = blockIdx.x, tid = threadIdx.x;
    int lane = tid & 31, warp = tid >> 5;
    __shared__ int warp_cnt[8];
    __shared__ int base_s;
    if (tid == 0) base_s = 0;
    __syncthreads();
    for (int c = 0; c < NPAIR; c += 256) {
        int i = c + tid;
        bool m = (g_pidx[i] == e);
        unsigned bal = __ballot_sync(0xffffffffu, m);
        if (lane == 0) warp_cnt[warp] = __popc(bal);
        __syncthreads();
        int pos = base_s;
        for (int w = 0; w < warp; w++) pos += warp_cnt[w];
        pos += __popc(bal & ((1u << lane) - 1u));
        if (m) { g_plist[e][pos] = i; g_wlist[e][pos] = g_pw[i]; }
        __syncthreads();
        if (tid == 0) {
            int tot = 0;
            #pragma unroll
            for (int w = 0; w < 8; w++) tot += warp_cnt[w];
            base_s += tot;
        }
        __syncthreads();
    }
    if (tid == 0) g_count[e] = base_s;
}

// ---------------- UP GEMM: h = silu(x W1^T) * (x W3^T) ----------------
// Stage layout (bytes): Ah 0, Al 18432, B1h 36864, B1l 46080, B3h 55296, B3l 64512
#define UP_STG 73728
#define UP_SMEM (1024 + 2*UP_STG)

__global__ __launch_bounds__(256, 1) void ffn_up_mma(const float* __restrict__ W1,
                                                     const float* __restrict__ W3) {
    int e = blockIdx.z;
    int cnt = g_count[e];
    int m0 = blockIdx.x * BM;
    if (m0 >= cnt) return;
    int n0 = blockIdx.y * BN;

    extern __shared__ __align__(128) char smem[];
    int* ps = (int*)smem;
    int tid = threadIdx.x;
    if (tid < BM) { int s = m0 + tid; ps[tid] = (s < cnt) ? g_plist[e][s] : -1; }
    __syncthreads();

    char* tiles = smem + 1024;
    uint32_t tiles_u = smem_u32(tiles);
    const float* W1e = W1 + (size_t)e * H * D + (size_t)n0 * D;
    const float* W3e = W3 + (size_t)e * H * D + (size_t)n0 * D;
    const int NS = D / BK;  // 16

    // pair mapping for B loads: this thread's 2 pairs (pair = 8 consecutive k floats)
    int pr0 = (tid * 2) >> 3, pc0 = (tid * 2) & 7;       // row, chunk of pair 0
    int pr1 = (tid * 2 + 1) >> 3, pc1 = (tid * 2 + 1) & 7;

    auto issueA = [&](int s) {
        uint32_t tb = tiles_u + (s & 1) * UP_STG;
        int k0 = s * BK;
        #pragma unroll
        for (int j = 0; j < 8; j++) {
            int idx = tid + j * 256;
            int part = idx >> 10, rem = idx & 1023, r = rem >> 3, c = rem & 7;
            int pr = ps[r];
            int tok = (pr < 0) ? 0 : (pr >> 1);
            const __nv_bfloat16* src = (part ? g_xl : g_xh) + (size_t)tok * D + k0 + c * 8;
            cp16(tb + part * 18432 + r * STRIDE + c * 16, src);
        }
    };
    auto ldgB = [&](int s, float4* r1, float4* r3) {
        int k0 = s * BK;
        const float* a0 = W1e + (size_t)pr0 * D + k0 + pc0 * 8;
        const float* a1 = W1e + (size_t)pr1 * D + k0 + pc1 * 8;
        const float* c0 = W3e + (size_t)pr0 * D + k0 + pc0 * 8;
        const float* c1 = W3e + (size_t)pr1 * D + k0 + pc1 * 8;
        r1[0] = ((const float4*)a0)[0]; r1[1] = ((const float4*)a0)[1];
        r1[2] = ((const float4*)a1)[0]; r1[3] = ((const float4*)a1)[1];
        r3[0] = ((const float4*)c0)[0]; r3[1] = ((const float4*)c0)[1];
        r3[2] = ((const float4*)c1)[0]; r3[3] = ((const float4*)c1)[1];
    };
    auto stsB = [&](int s, const float4* r1, const float4* r3) {
        char* tb = tiles + (s & 1) * UP_STG;
        uint4 hi, lo;
        cvt_pair(r1[0], r1[1], hi, lo);
        *(uint4*)(tb + 36864 + pr0 * STRIDE + pc0 * 16) = hi;
        *(uint4*)(tb + 46080 + pr0 * STRIDE + pc0 * 16) = lo;
        cvt_pair(r1[2], r1[3], hi, lo);
        *(uint4*)(tb + 36864 + pr1 * STRIDE + pc1 * 16) = hi;
        *(uint4*)(tb + 46080 + pr1 * STRIDE + pc1 * 16) = lo;
        cvt_pair(r3[0], r3[1], hi, lo);
        *(uint4*)(tb + 55296 + pr0 * STRIDE + pc0 * 16) = hi;
        *(uint4*)(tb + 64512 + pr0 * STRIDE + pc0 * 16) = lo;
        cvt_pair(r3[2], r3[3], hi, lo);
        *(uint4*)(tb + 55296 + pr1 * STRIDE + pc1 * 16) = hi;
        *(uint4*)(tb + 64512 + pr1 * STRIDE + pc1 * 16) = lo;
    };

    int wid = tid >> 5, lane = tid & 31;
    int wm = wid & 3, wn = wid >> 2;
    int g = lane >> 2, q = lane & 3;

    float a1[2][4][4], a3[2][4][4];
    #pragma unroll
    for (int i = 0; i < 2; i++)
        #pragma unroll
        for (int j = 0; j < 4; j++)
            #pragma unroll
            for (int k = 0; k < 4; k++) { a1[i][j][k] = 0.f; a3[i][j][k] = 0.f; }

    issueA(0); CP_COMMIT();
    issueA(1); CP_COMMIT();
    float4 rB1[4], rB3[4];
    ldgB(0, rB1, rB3);

    for (int s = 0; s < NS; s++) {
        stsB(s, rB1, rB3);
        if (s + 1 < NS) ldgB(s + 1, rB1, rB3);
        CP_WAIT1();
        __syncthreads();
        const char* tb = tiles + (s & 1) * UP_STG;
        const char* Ah = tb,           *Al  = tb + 18432;
        const char* B1h = tb + 36864,  *B1l = tb + 46080;
        const char* B3h = tb + 55296,  *B3l = tb + 64512;
        #pragma unroll
        for (int kk = 0; kk < BK; kk += 16) {
            uint32_t fAh[2][4], fAl[2][4];
            #pragma unroll
            for (int mi = 0; mi < 2; mi++) {
                ldA(fAh[mi], Ah, wm * 32 + mi * 16, kk, g, q);
                ldA(fAl[mi], Al, wm * 32 + mi * 16, kk, g, q);
            }
            {
                uint32_t bh[4][2], bl[4][2];
                #pragma unroll
                for (int nj = 0; nj < 4; nj++) {
                    ldB(bh[nj], B1h, wn * 32 + nj * 8, kk, g, q);
                    ldB(bl[nj], B1l, wn * 32 + nj * 8, kk, g, q);
                }
                #pragma unroll
                for (int mi = 0; mi < 2; mi++)
                    #pragma unroll
                    for (int nj = 0; nj < 4; nj++) {
                        mma16816(a1[mi][nj], fAh[mi], bh[nj]);
                        mma16816(a1[mi][nj], fAh[mi], bl[nj]);
                        mma16816(a1[mi][nj], fAl[mi], bh[nj]);
                    }
            }
            {
                uint32_t bh[4][2], bl[4][2];
                #pragma unroll
                for (int nj = 0; nj < 4; nj++) {
                    ldB(bh[nj], B3h, wn * 32 + nj * 8, kk, g, q);
                    ldB(bl[nj], B3l, wn * 32 + nj * 8, kk, g, q);
                }
                #pragma unroll
                for (int mi = 0; mi < 2; mi++)
                    #pragma unroll
                    for (int nj = 0; nj < 4; nj++) {
                        mma16816(a3[mi][nj], fAh[mi], bh[nj]);
                        mma16816(a3[mi][nj], fAh[mi], bl[nj]);
                        mma16816(a3[mi][nj], fAl[mi], bh[nj]);
                    }
            }
        }
        __syncthreads();
        if (s + 2 < NS) issueA(s + 2);
        CP_COMMIT();
    }

    // epilogue: silu(z)*u, split to hi/lo, store bf16x2
    #pragma unroll
    for (int mi = 0; mi < 2; mi++) {
        #pragma unroll
        for (int nj = 0; nj < 4; nj++) {
            int lr0 = wm * 32 + mi * 16 + g, lr1 = lr0 + 8;
            int n = n0 + wn * 32 + nj * 8 + q * 2;
            float* c1 = a1[mi][nj];
            float* c3 = a3[mi][nj];
            #pragma unroll
            for (int half = 0; half < 2; half++) {
                int p = ps[half ? lr1 : lr0];
                if (p < 0) continue;
                float z0 = c1[half * 2], z1 = c1[half * 2 + 1];
                float u0 = c3[half * 2], u1 = c3[half * 2 + 1];
                float h0 = (z0 / (1.f + __expf(-z0))) * u0;
                float h1 = (z1 / (1.f + __expf(-z1))) * u1;
                __nv_bfloat162 hh = __floats2bfloat162_rn(h0, h1);
                __nv_bfloat162 ll = __floats2bfloat162_rn(h0 - __bfloat162float(hh.x),
                                                          h1 - __bfloat162float(hh.y));
                *(uint32_t*)(g_hh + (size_t)p * H + n) = b2u(hh);
                *(uint32_t*)(g_hl + (size_t)p * H + n) = b2u(ll);
            }
        }
    }
}

// ---------------- DOWN GEMM: yp = w * (h W2^T) ----------------
// Stage layout: Ah 0, Al 18432, Bh 36864, Bl 46080
#define DN_STG 55296
#define DN_SMEM (1024 + 2*DN_STG)

__global__ __launch_bounds__(256, 1) void ffn_down_mma(const float* __restrict__ W2) {
    int e = blockIdx.z;
    int cnt = g_count[e];
    int m0 = blockIdx.x * BM;
    if (m0 >= cnt) return;
    int n0 = blockIdx.y * BN;

    extern __shared__ __align__(128) char smem[];
    int* ps = (int*)smem;
    float* pwS = (float*)(smem + 512);
    int tid = threadIdx.x;
    if (tid < BM) {
        int s = m0 + tid;
        if (s < cnt) { ps[tid] = g_plist[e][s]; pwS[tid] = g_wlist[e][s]; }
        else         { ps[tid] = -1;            pwS[tid] = 0.f; }
    }
    __syncthreads();

    char* tiles = smem + 1024;
    uint32_t tiles_u = smem_u32(tiles);
    const float* W2e = W2 + (size_t)e * D * H + (size_t)n0 * H;
    const int NS = H / BK;  // 44

    int pr0 = (tid * 2) >> 3, pc0 = (tid * 2) & 7;
    int pr1 = (tid * 2 + 1) >> 3, pc1 = (tid * 2 + 1) & 7;

    auto issueA = [&](int s) {
        uint32_t tb = tiles_u + (s & 1) * DN_STG;
        int k0 = s * BK;
        #pragma unroll
        for (int j = 0; j < 8; j++) {
            int idx = tid + j * 256;
            int part = idx >> 10, rem = idx & 1023, r = rem >> 3, c = rem & 7;
            int p = ps[r];
            int pr = (p < 0) ? 0 : p;
            const __nv_bfloat16* src = (part ? g_hl : g_hh) + (size_t)pr * H + k0 + c * 8;
            cp16(tb + part * 18432 + r * STRIDE + c * 16, src);
        }
    };
    auto ldgB = [&](int s, float4* r2) {
        int k0 = s * BK;
        const float* a0 = W2e + (size_t)pr0 * H + k0 + pc0 * 8;
        const float* a1 = W2e + (size_t)pr1 * H + k0 + pc1 * 8;
        r2[0] = ((const float4*)a0)[0]; r2[1] = ((const float4*)a0)[1];
        r2[2] = ((const float4*)a1)[0]; r2[3] = ((const float4*)a1)[1];
    };
    auto stsB = [&](int s, const float4* r2) {
        char* tb = tiles + (s & 1) * DN_STG;
        uint4 hi, lo;
        cvt_pair(r2[0], r2[1], hi, lo);
        *(uint4*)(tb + 36864 + pr0 * STRIDE + pc0 * 16) = hi;
        *(uint4*)(tb + 46080 + pr0 * STRIDE + pc0 * 16) = lo;
        cvt_pair(r2[2], r2[3], hi, lo);
        *(uint4*)(tb + 36864 + pr1 * STRIDE + pc1 * 16) = hi;
        *(uint4*)(tb + 46080 + pr1 * STRIDE + pc1 * 16) = lo;
    };

    int wid = tid >> 5, lane = tid & 31;
    int wm = wid & 3, wn = wid >> 2;
    int g = lane >> 2, q = lane & 3;

    float acc[2][4][4];
    #pragma unroll
    for (int i = 0; i < 2; i++)
        #pragma unroll
        for (int j = 0; j < 4; j++)
            #pragma unroll
            for (int k = 0; k < 4; k++) acc[i][j][k] = 0.f;

    issueA(0); CP_COMMIT();
    issueA(1); CP_COMMIT();
    float4 rB[4];
    ldgB(0, rB);

    for (int s = 0; s < NS; s++) {
        stsB(s, rB);
        if (s + 1 < NS) ldgB(s + 1, rB);
        CP_WAIT1();
        __syncthreads();
        const char* tb = tiles + (s & 1) * DN_STG;
        const char* Ah = tb,          *Al = tb + 18432;
        const char* Bh = tb + 36864,  *Bl = tb + 46080;
        #pragma unroll
        for (int kk = 0; kk < BK; kk += 16) {
            uint32_t fAh[2][4], fAl[2][4];
            #pragma unroll
            for (int mi = 0; mi < 2; mi++) {
                ldA(fAh[mi], Ah, wm * 32 + mi * 16, kk, g, q);
                ldA(fAl[mi], Al, wm * 32 + mi * 16, kk, g, q);
            }
            uint32_t bh[4][2], bl[4][2];
            #pragma unroll
            for (int nj = 0; nj < 4; nj++) {
                ldB(bh[nj], Bh, wn * 32 + nj * 8, kk, g, q);
                ldB(bl[nj], Bl, wn * 32 + nj * 8, kk, g, q);
            }
            #pragma unroll
            for (int mi = 0; mi < 2; mi++)
                #pragma unroll
                for (int nj = 0; nj < 4; nj++) {
                    mma16816(acc[mi][nj], fAh[mi], bh[nj]);
                    mma16816(acc[mi][nj], fAh[mi], bl[nj]);
                    mma16816(acc[mi][nj], fAl[mi], bh[nj]);
                }
        }
        __syncthreads();
        if (s + 2 < NS) issueA(s + 2);
        CP_COMMIT();
    }

    #pragma unroll
    for (int mi = 0; mi < 2; mi++) {
        #pragma unroll
        for (int nj = 0; nj < 4; nj++) {
            int lr0 = wm * 32 + mi * 16 + g, lr1 = lr0 + 8;
            int n = n0 + wn * 32 + nj * 8 + q * 2;
            float* c = acc[mi][nj];
            #pragma unroll
            for (int half = 0; half < 2; half++) {
                int lr = half ? lr1 : lr0;
                int p = ps[lr];
                if (p < 0) continue;
                float w = pwS[lr];
                float2 v = make_float2(w * c[half * 2], w * c[half * 2 + 1]);
                *(float2*)(g_yp + (size_t)p * D + n) = v;
            }
        }
    }
}

// ---------------- combine ----------------
__global__ void combine_kernel(float* __restrict__ y) {
    int i = blockIdx.x * 256 + threadIdx.x;
    int t = i / D, d = i - t * D;
    y[i] = g_yp[(size_t)(2 * t) * D + d] + g_yp[(size_t)(2 * t + 1) * D + d];
}

// ---------------- launch ----------------
extern "C" void kernel_launch(void* const* d_in, const int* in_sizes, int n_in,
                              void* d_out, int out_size) {
    const float* x  = (const float*)d_in[0];
    const float* Wg = (const float*)d_in[1];
    const float* W1 = (const float*)d_in[2];
    const float* W2 = (const float*)d_in[3];
    const float* W3 = (const float*)d_in[4];
    float* y = (float*)d_out;

    cudaFuncSetAttribute(ffn_up_mma,   cudaFuncAttributeMaxDynamicSharedMemorySize, UP_SMEM);
    cudaFuncSetAttribute(ffn_down_mma, cudaFuncAttributeMaxDynamicSharedMemorySize, DN_SMEM);

    // pre-split x only (tiny)
    {
        int nX = T * D / 4;
        __nv_bfloat16 *xh, *xl;
        cudaGetSymbolAddress((void**)&xh, g_xh);
        cudaGetSymbolAddress((void**)&xl, g_xl);
        split_kernel<<<(nX + 255) / 256, 256>>>(x, xh, xl, nX);
    }

    gate_kernel<<<T, 256>>>(x, Wg);
    build_lists_kernel<<<E, 256>>>();

    dim3 g1(T / BM, H / BN, E);   // 16 x 44 x 8
    ffn_up_mma<<<g1, 256, UP_SMEM>>>(W1, W3);

    dim3 g2(T / BM, D / BN, E);   // 16 x 16 x 8
    ffn_down_mma<<<g2, 256, DN_SMEM>>>(W2);

    combine_kernel<<<(T * D) / 256, 256>>>(y);
}

// round 5
// speedup vs baseline: 1.1577x; 1.1577x over previous
#include <cuda_runtime.h>
#include <cuda_bf16.h>
#include <cstdint>
#include <math.h>

#define T 2048      // tokens
#define D 1024      // model dim
#define H 2816      // ffn hidden
#define E 8         // experts
#define NPAIR (T*2) // token-expert pairs

#define BM 128
#define BN 64
#define BK 64
#define STRIDE 144  // padded bytes per k-row: 64*2 + 16 (bank-conflict-free)

// ---------------- device globals (no allocation allowed) ----------------
__device__ int   g_pidx[NPAIR];
__device__ float g_pw[NPAIR];
__device__ int   g_count[E];
__device__ int   g_plist[E][T];
__device__ float g_wlist[E][T];

__device__ __align__(16) __nv_bfloat16 g_xh[T*D],  g_xl[T*D];
__device__ __align__(16) __nv_bfloat16 g_W1h[(size_t)E*H*D], g_W1l[(size_t)E*H*D];
__device__ __align__(16) __nv_bfloat16 g_W3h[(size_t)E*H*D], g_W3l[(size_t)E*H*D];
__device__ __align__(16) __nv_bfloat16 g_W2h[(size_t)E*D*H], g_W2l[(size_t)E*D*H];
__device__ __align__(16) __nv_bfloat16 g_hh[(size_t)NPAIR*H], g_hl[(size_t)NPAIR*H];
__device__ float g_yp[(size_t)NPAIR*D];

// ---------------- helpers ----------------
__device__ __forceinline__ uint32_t smem_u32(const void* p) {
    uint32_t a;
    asm("{ .reg .u64 t; cvta.to.shared.u64 t, %1; cvt.u32.u64 %0, t; }" : "=r"(a) : "l"(p));
    return a;
}
__device__ __forceinline__ void cp16(uint32_t dst, const void* src) {
    asm volatile("cp.async.cg.shared.global [%0], [%1], 16;" :: "r"(dst), "l"(src));
}
#define CP_COMMIT() asm volatile("cp.async.commit_group;" ::: "memory")
#define CP_WAIT1()  asm volatile("cp.async.wait_group 1;" ::: "memory")

__device__ __forceinline__ void mma16816(float* c, const uint32_t* a, const uint32_t* b) {
    asm volatile("mma.sync.aligned.m16n8k16.row.col.f32.bf16.bf16.f32 "
        "{%0,%1,%2,%3}, {%4,%5,%6,%7}, {%8,%9}, {%0,%1,%2,%3};"
        : "+f"(c[0]), "+f"(c[1]), "+f"(c[2]), "+f"(c[3])
        : "r"(a[0]), "r"(a[1]), "r"(a[2]), "r"(a[3]), "r"(b[0]), "r"(b[1]));
}
__device__ __forceinline__ void ldA(uint32_t* a, const char* tile, int rm, int kk, int g, int q) {
    const char* p = tile + (rm + g) * STRIDE + (kk + q * 2) * 2;
    a[0] = *(const uint32_t*)p;
    a[1] = *(const uint32_t*)(p + 8 * STRIDE);
    a[2] = *(const uint32_t*)(p + 16);
    a[3] = *(const uint32_t*)(p + 8 * STRIDE + 16);
}
__device__ __forceinline__ void ldB(uint32_t* b, const char* tile, int cn, int kk, int g, int q) {
    const char* p = tile + (cn + g) * STRIDE + (kk + q * 2) * 2;
    b[0] = *(const uint32_t*)p;
    b[1] = *(const uint32_t*)(p + 16);
}
__device__ __forceinline__ uint32_t b2u(__nv_bfloat162 v) { return *reinterpret_cast<uint32_t*>(&v); }

// split 8 fp32 (two float4) into 8 bf16 hi + 8 bf16 lo
__device__ __forceinline__ void cvt_pair(const float4 A, const float4 B, uint4& hi, uint4& lo) {
    __nv_bfloat162 h0 = __floats2bfloat162_rn(A.x, A.y);
    __nv_bfloat162 h1 = __floats2bfloat162_rn(A.z, A.w);
    __nv_bfloat162 h2 = __floats2bfloat162_rn(B.x, B.y);
    __nv_bfloat162 h3 = __floats2bfloat162_rn(B.z, B.w);
    __nv_bfloat162 l0 = __floats2bfloat162_rn(A.x - __bfloat162float(h0.x), A.y - __bfloat162float(h0.y));
    __nv_bfloat162 l1 = __floats2bfloat162_rn(A.z - __bfloat162float(h1.x), A.w - __bfloat162float(h1.y));
    __nv_bfloat162 l2 = __floats2bfloat162_rn(B.x - __bfloat162float(h2.x), B.y - __bfloat162float(h2.y));
    __nv_bfloat162 l3 = __floats2bfloat162_rn(B.z - __bfloat162float(h3.x), B.w - __bfloat162float(h3.y));
    hi = make_uint4(b2u(h0), b2u(h1), b2u(h2), b2u(h3));
    lo = make_uint4(b2u(l0), b2u(l1), b2u(l2), b2u(l3));
}

// ---------------- split fp32 -> bf16 hi/lo, 4-way strip-mined (MLP=8) ----------------
// q = number of 8-float groups per strip; total groups = 4*q. Grid covers q.
__global__ __launch_bounds__(256) void split4_kernel(const float4* __restrict__ src,
                                                     uint4* __restrict__ hi,
                                                     uint4* __restrict__ lo, int q) {
    int i = blockIdx.x * 256 + threadIdx.x;
    if (i >= q) return;
    // front-batch 8 independent LDG.128
    float4 a0 = src[2*(size_t)i],             b0 = src[2*(size_t)i + 1];
    float4 a1 = src[2*((size_t)i + q)],       b1 = src[2*((size_t)i + q) + 1];
    float4 a2 = src[2*((size_t)i + 2*q)],     b2 = src[2*((size_t)i + 2*q) + 1];
    float4 a3 = src[2*((size_t)i + 3*q)],     b3 = src[2*((size_t)i + 3*q) + 1];
    uint4 h, l;
    cvt_pair(a0, b0, h, l); hi[i]         = h; lo[i]         = l;
    cvt_pair(a1, b1, h, l); hi[i + q]     = h; lo[i + q]     = l;
    cvt_pair(a2, b2, h, l); hi[i + 2*q]   = h; lo[i + 2*q]   = l;
    cvt_pair(a3, b3, h, l); hi[i + 3*q]   = h; lo[i + 3*q]   = l;
}

// ---------------- gate / routing ----------------
__global__ void gate_kernel(const float* __restrict__ x, const float* __restrict__ Wg) {
    int t = blockIdx.x;
    int warp = threadIdx.x >> 5, lane = threadIdx.x & 31;
    __shared__ float logits[E];
    const float* xr = x + (size_t)t * D;
    const float* wr = Wg + (size_t)warp * D;
    float s = 0.f;
    #pragma unroll
    for (int j = 0; j < D / 128; j++) {
        int i = lane * 4 + j * 128;
        float4 xv = *(const float4*)(xr + i);
        float4 wv = *(const float4*)(wr + i);
        s += xv.x * wv.x + xv.y * wv.y + xv.z * wv.z + xv.w * wv.w;
    }
    #pragma unroll
    for (int o = 16; o; o >>= 1) s += __shfl_xor_sync(0xffffffffu, s, o);
    if (lane == 0) logits[warp] = s;
    __syncthreads();
    if (threadIdx.x == 0) {
        float m = logits[0];
        #pragma unroll
        for (int e2 = 1; e2 < E; e2++) m = fmaxf(m, logits[e2]);
        float p[E];
        #pragma unroll
        for (int e2 = 0; e2 < E; e2++) p[e2] = expf(logits[e2] - m);
        int i0 = 0;
        #pragma unroll
        for (int e2 = 1; e2 < E; e2++) if (p[e2] > p[i0]) i0 = e2;
        int i1 = (i0 == 0) ? 1 : 0;
        #pragma unroll
        for (int e2 = 0; e2 < E; e2++) if (e2 != i0 && p[e2] > p[i1]) i1 = e2;
        float inv = 1.f / (p[i0] + p[i1]);
        g_pidx[2*t]   = i0; g_pw[2*t]   = p[i0] * inv;
        g_pidx[2*t+1] = i1; g_pw[2*t+1] = p[i1] * inv;
    }
}

__global__ void build_lists_kernel() {
    int e = blockIdx.x, tid = threadIdx.x;
    int lane = tid & 31, warp = tid >> 5;
    __shared__ int warp_cnt[8];
    __shared__ int base_s;
    if (tid == 0) base_s = 0;
    __syncthreads();
    for (int c = 0; c < NPAIR; c += 256) {
        int i = c + tid;
        bool m = (g_pidx[i] == e);
        unsigned bal = __ballot_sync(0xffffffffu, m);
        if (lane == 0) warp_cnt[warp] = __popc(bal);
        __syncthreads();
        int pos = base_s;
        for (int w = 0; w < warp; w++) pos += warp_cnt[w];
        pos += __popc(bal & ((1u << lane) - 1u));
        if (m) { g_plist[e][pos] = i; g_wlist[e][pos] = g_pw[i]; }
        __syncthreads();
        if (tid == 0) {
            int tot = 0;
            #pragma unroll
            for (int w = 0; w < 8; w++) tot += warp_cnt[w];
            base_s += tot;
        }
        __syncthreads();
    }
    if (tid == 0) g_count[e] = base_s;
}

// ---------------- UP GEMM: h = silu(x W1^T) * (x W3^T), split-bf16 mma ----------------
// Stage layout (bytes): Ah 0, Al 18432, B1h 36864, B1l 46080, B3h 55296, B3l 64512
#define UP_STG 73728
#define UP_SMEM (1024 + 2*UP_STG)

__global__ __launch_bounds__(256, 1) void ffn_up_mma() {
    int e = blockIdx.z;
    int cnt = g_count[e];
    int m0 = blockIdx.x * BM;
    if (m0 >= cnt) return;
    int n0 = blockIdx.y * BN;

    extern __shared__ __align__(128) char smem[];
    int* ps = (int*)smem;
    int tid = threadIdx.x;
    if (tid < BM) { int s = m0 + tid; ps[tid] = (s < cnt) ? g_plist[e][s] : -1; }
    __syncthreads();

    char* tiles = smem + 1024;
    uint32_t tiles_u = smem_u32(tiles);
    const size_t wbase = (size_t)e * H * D + (size_t)n0 * D;
    const int NS = D / BK;  // 16

    auto issue = [&](int s) {
        uint32_t tb = tiles_u + (s & 1) * UP_STG;
        int k0 = s * BK;
        #pragma unroll
        for (int j = 0; j < 16; j++) {
            int idx = tid + j * 256;
            if (idx < 2048) {  // A: x rows gathered by pair
                int part = idx >> 10, rem = idx & 1023, r = rem >> 3, c = rem & 7;
                int pr = ps[r];
                int tok = (pr < 0) ? 0 : (pr >> 1);
                const __nv_bfloat16* src = (part ? g_xl : g_xh) + (size_t)tok * D + k0 + c * 8;
                cp16(tb + part * 18432 + r * STRIDE + c * 16, src);
            } else {           // B: W1 / W3 rows
                int idx2 = idx - 2048;
                int mat = idx2 >> 10, rem = idx2 & 1023, part = rem >> 9, r = (rem >> 3) & 63, c = rem & 7;
                const __nv_bfloat16* base = mat ? (part ? g_W3l : g_W3h) : (part ? g_W1l : g_W1h);
                cp16(tb + 36864 + mat * 18432 + part * 9216 + r * STRIDE + c * 16,
                     base + wbase + (size_t)r * D + k0 + c * 8);
            }
        }
    };

    int wid = tid >> 5, lane = tid & 31;
    int wm = wid & 3, wn = wid >> 2;
    int g = lane >> 2, q = lane & 3;

    float a1[2][4][4], a3[2][4][4];
    #pragma unroll
    for (int i = 0; i < 2; i++)
        #pragma unroll
        for (int j = 0; j < 4; j++)
            #pragma unroll
            for (int k = 0; k < 4; k++) { a1[i][j][k] = 0.f; a3[i][j][k] = 0.f; }

    issue(0); CP_COMMIT();
    issue(1); CP_COMMIT();

    for (int s = 0; s < NS; s++) {
        CP_WAIT1();
        __syncthreads();
        const char* tb = tiles + (s & 1) * UP_STG;
        const char* Ah = tb,           *Al  = tb + 18432;
        const char* B1h = tb + 36864,  *B1l = tb + 46080;
        const char* B3h = tb + 55296,  *B3l = tb + 64512;
        #pragma unroll
        for (int kk = 0; kk < BK; kk += 16) {
            uint32_t fAh[2][4], fAl[2][4];
            #pragma unroll
            for (int mi = 0; mi < 2; mi++) {
                ldA(fAh[mi], Ah, wm * 32 + mi * 16, kk, g, q);
                ldA(fAl[mi], Al, wm * 32 + mi * 16, kk, g, q);
            }
            {   // W1
                uint32_t bh[4][2], bl[4][2];
                #pragma unroll
                for (int nj = 0; nj < 4; nj++) {
                    ldB(bh[nj], B1h, wn * 32 + nj * 8, kk, g, q);
                    ldB(bl[nj], B1l, wn * 32 + nj * 8, kk, g, q);
                }
                #pragma unroll
                for (int mi = 0; mi < 2; mi++)
                    #pragma unroll
                    for (int nj = 0; nj < 4; nj++) {
                        mma16816(a1[mi][nj], fAh[mi], bh[nj]);
                        mma16816(a1[mi][nj], fAh[mi], bl[nj]);
                        mma16816(a1[mi][nj], fAl[mi], bh[nj]);
                    }
            }
            {   // W3
                uint32_t bh[4][2], bl[4][2];
                #pragma unroll
                for (int nj = 0; nj < 4; nj++) {
                    ldB(bh[nj], B3h, wn * 32 + nj * 8, kk, g, q);
                    ldB(bl[nj], B3l, wn * 32 + nj * 8, kk, g, q);
                }
                #pragma unroll
                for (int mi = 0; mi < 2; mi++)
                    #pragma unroll
                    for (int nj = 0; nj < 4; nj++) {
                        mma16816(a3[mi][nj], fAh[mi], bh[nj]);
                        mma16816(a3[mi][nj], fAh[mi], bl[nj]);
                        mma16816(a3[mi][nj], fAl[mi], bh[nj]);
                    }
            }
        }
        __syncthreads();
        if (s + 2 < NS) issue(s + 2);
        CP_COMMIT();
    }

    // epilogue: silu(z)*u, split to hi/lo, store bf16x2
    #pragma unroll
    for (int mi = 0; mi < 2; mi++) {
        #pragma unroll
        for (int nj = 0; nj < 4; nj++) {
            int lr0 = wm * 32 + mi * 16 + g, lr1 = lr0 + 8;
            int n = n0 + wn * 32 + nj * 8 + q * 2;
            float* c1 = a1[mi][nj];
            float* c3 = a3[mi][nj];
            #pragma unroll
            for (int half = 0; half < 2; half++) {
                int p = ps[half ? lr1 : lr0];
                if (p < 0) continue;
                float z0 = c1[half * 2], z1 = c1[half * 2 + 1];
                float u0 = c3[half * 2], u1 = c3[half * 2 + 1];
                float h0 = (z0 / (1.f + __expf(-z0))) * u0;
                float h1 = (z1 / (1.f + __expf(-z1))) * u1;
                __nv_bfloat162 hh = __floats2bfloat162_rn(h0, h1);
                __nv_bfloat162 ll = __floats2bfloat162_rn(h0 - __bfloat162float(hh.x),
                                                          h1 - __bfloat162float(hh.y));
                *(uint32_t*)(g_hh + (size_t)p * H + n) = b2u(hh);
                *(uint32_t*)(g_hl + (size_t)p * H + n) = b2u(ll);
            }
        }
    }
}

// ---------------- DOWN GEMM: yp = w * (h W2^T), split-bf16 mma ----------------
// Stage layout: Ah 0, Al 18432, Bh 36864, Bl 46080
#define DN_STG 55296
#define DN_SMEM (1024 + 2*DN_STG)

__global__ __launch_bounds__(256, 1) void ffn_down_mma() {
    int e = blockIdx.z;
    int cnt = g_count[e];
    int m0 = blockIdx.x * BM;
    if (m0 >= cnt) return;
    int n0 = blockIdx.y * BN;

    extern __shared__ __align__(128) char smem[];
    int* ps = (int*)smem;
    float* pwS = (float*)(smem + 512);
    int tid = threadIdx.x;
    if (tid < BM) {
        int s = m0 + tid;
        if (s < cnt) { ps[tid] = g_plist[e][s]; pwS[tid] = g_wlist[e][s]; }
        else         { ps[tid] = -1;            pwS[tid] = 0.f; }
    }
    __syncthreads();

    char* tiles = smem + 1024;
    uint32_t tiles_u = smem_u32(tiles);
    const size_t wbase = (size_t)e * D * H + (size_t)n0 * H;
    const int NS = H / BK;  // 44

    auto issue = [&](int s) {
        uint32_t tb = tiles_u + (s & 1) * DN_STG;
        int k0 = s * BK;
        #pragma unroll
        for (int j = 0; j < 12; j++) {
            int idx = tid + j * 256;
            if (idx < 2048) {  // A: h rows by pair
                int part = idx >> 10, rem = idx & 1023, r = rem >> 3, c = rem & 7;
                int p = ps[r];
                int pr = (p < 0) ? 0 : p;
                const __nv_bfloat16* src = (part ? g_hl : g_hh) + (size_t)pr * H + k0 + c * 8;
                cp16(tb + part * 18432 + r * STRIDE + c * 16, src);
            } else {           // B: W2 rows
                int idx2 = idx - 2048;
                int part = idx2 >> 9, r = (idx2 >> 3) & 63, c = idx2 & 7;
                const __nv_bfloat16* base = part ? g_W2l : g_W2h;
                cp16(tb + 36864 + part * 9216 + r * STRIDE + c * 16,
                     base + wbase + (size_t)r * H + k0 + c * 8);
            }
        }
    };

    int wid = tid >> 5, lane = tid & 31;
    int wm = wid & 3, wn = wid >> 2;
    int g = lane >> 2, q = lane & 3;

    float acc[2][4][4];
    #pragma unroll
    for (int i = 0; i < 2; i++)
        #pragma unroll
        for (int j = 0; j < 4; j++)
            #pragma unroll
            for (int k = 0; k < 4; k++) acc[i][j][k] = 0.f;

    issue(0); CP_COMMIT();
    issue(1); CP_COMMIT();

    for (int s = 0; s < NS; s++) {
        CP_WAIT1();
        __syncthreads();
        const char* tb = tiles + (s & 1) * DN_STG;
        const char* Ah = tb,          *Al = tb + 18432;
        const char* Bh = tb + 36864,  *Bl = tb + 46080;
        #pragma unroll
        for (int kk = 0; kk < BK; kk += 16) {
            uint32_t fAh[2][4], fAl[2][4];
            #pragma unroll
            for (int mi = 0; mi < 2; mi++) {
                ldA(fAh[mi], Ah, wm * 32 + mi * 16, kk, g, q);
                ldA(fAl[mi], Al, wm * 32 + mi * 16, kk, g, q);
            }
            uint32_t bh[4][2], bl[4][2];
            #pragma unroll
            for (int nj = 0; nj < 4; nj++) {
                ldB(bh[nj], Bh, wn * 32 + nj * 8, kk, g, q);
                ldB(bl[nj], Bl, wn * 32 + nj * 8, kk, g, q);
            }
            #pragma unroll
            for (int mi = 0; mi < 2; mi++)
                #pragma unroll
                for (int nj = 0; nj < 4; nj++) {
                    mma16816(acc[mi][nj], fAh[mi], bh[nj]);
                    mma16816(acc[mi][nj], fAh[mi], bl[nj]);
                    mma16816(acc[mi][nj], fAl[mi], bh[nj]);
                }
        }
        __syncthreads();
        if (s + 2 < NS) issue(s + 2);
        CP_COMMIT();
    }

    #pragma unroll
    for (int mi = 0; mi < 2; mi++) {
        #pragma unroll
        for (int nj = 0; nj < 4; nj++) {
            int lr0 = wm * 32 + mi * 16 + g, lr1 = lr0 + 8;
            int n = n0 + wn * 32 + nj * 8 + q * 2;
            float* c = acc[mi][nj];
            #pragma unroll
            for (int half = 0; half < 2; half++) {
                int lr = half ? lr1 : lr0;
                int p = ps[lr];
                if (p < 0) continue;
                float w = pwS[lr];
                float2 v = make_float2(w * c[half * 2], w * c[half * 2 + 1]);
                *(float2*)(g_yp + (size_t)p * D + n) = v;
            }
        }
    }
}

// ---------------- combine ----------------
__global__ void combine_kernel(float* __restrict__ y) {
    int i = blockIdx.x * 256 + threadIdx.x;
    int t = i / D, d = i - t * D;
    y[i] = g_yp[(size_t)(2 * t) * D + d] + g_yp[(size_t)(2 * t + 1) * D + d];
}

// ---------------- launch ----------------
extern "C" void kernel_launch(void* const* d_in, const int* in_sizes, int n_in,
                              void* d_out, int out_size) {
    const float* x  = (const float*)d_in[0];
    const float* Wg = (const float*)d_in[1];
    const float* W1 = (const float*)d_in[2];
    const float* W2 = (const float*)d_in[3];
    const float* W3 = (const float*)d_in[4];
    float* y = (float*)d_out;

    cudaFuncSetAttribute(ffn_up_mma,   cudaFuncAttributeMaxDynamicSharedMemorySize, UP_SMEM);
    cudaFuncSetAttribute(ffn_down_mma, cudaFuncAttributeMaxDynamicSharedMemorySize, DN_SMEM);

    // pre-split fp32 -> bf16 hi/lo (4-way strip-mined, MLP=8)
    {
        int qW = (int)((size_t)E * H * D / 8 / 4);   // 720,896 groups per strip
        int qX = T * D / 8 / 4;                      // 65,536
        __nv_bfloat16 *w1h, *w1l, *w3h, *w3l, *w2h, *w2l, *xh, *xl;
        cudaGetSymbolAddress((void**)&w1h, g_W1h); cudaGetSymbolAddress((void**)&w1l, g_W1l);
        cudaGetSymbolAddress((void**)&w3h, g_W3h); cudaGetSymbolAddress((void**)&w3l, g_W3l);
        cudaGetSymbolAddress((void**)&w2h, g_W2h); cudaGetSymbolAddress((void**)&w2l, g_W2l);
        cudaGetSymbolAddress((void**)&xh,  g_xh);  cudaGetSymbolAddress((void**)&xl,  g_xl);
        split4_kernel<<<(qW + 255) / 256, 256>>>((const float4*)W1, (uint4*)w1h, (uint4*)w1l, qW);
        split4_kernel<<<(qW + 255) / 256, 256>>>((const float4*)W3, (uint4*)w3h, (uint4*)w3l, qW);
        split4_kernel<<<(qW + 255) / 256, 256>>>((const float4*)W2, (uint4*)w2h, (uint4*)w2l, qW);
        split4_kernel<<<(qX + 255) / 256, 256>>>((const float4*)x,  (uint4*)xh,  (uint4*)xl,  qX);
    }

    gate_kernel<<<T, 256>>>(x, Wg);
    build_lists_kernel<<<E, 256>>>();

    dim3 g1(T / BM, H / BN, E);   // 16 x 44 x 8
    ffn_up_mma<<<g1, 256, UP_SMEM>>>();

    dim3 g2(T / BM, D / BN, E);   // 16 x 16 x 8
    ffn_down_mma<<<g2, 256, DN_SMEM>>>();

    combine_kernel<<<(T * D) / 256, 256>>>(y);
}

// round 6
// speedup vs baseline: 1.1606x; 1.0025x over previous
#include <cuda_runtime.h>
#include <cuda_bf16.h>
#include <cstdint>
#include <math.h>

#define T 2048      // tokens
#define D 1024      // model dim
#define H 2816      // ffn hidden
#define E 8         // experts
#define NPAIR (T*2) // token-expert pairs

#define BM 128
#define BN 64
#define BK 64
#define STRIDE 144  // padded bytes per k-row: 64*2 + 16 (bank-conflict-free)

// ---------------- device globals (no allocation allowed) ----------------
__device__ int   g_pidx[NPAIR];
__device__ float g_pw[NPAIR];
__device__ int   g_count[E];
__device__ int   g_plist[E][T];
__device__ float g_wlist[E][T];

__device__ __align__(16) __nv_bfloat16 g_xh[T*D],  g_xl[T*D];
__device__ __align__(16) __nv_bfloat16 g_W1h[(size_t)E*H*D], g_W1l[(size_t)E*H*D];
__device__ __align__(16) __nv_bfloat16 g_W3h[(size_t)E*H*D], g_W3l[(size_t)E*H*D];
__device__ __align__(16) __nv_bfloat16 g_W2h[(size_t)E*D*H], g_W2l[(size_t)E*D*H];
__device__ __align__(16) __nv_bfloat16 g_hh[(size_t)NPAIR*H], g_hl[(size_t)NPAIR*H];
__device__ float g_yp[(size_t)NPAIR*D];

// ---------------- helpers ----------------
__device__ __forceinline__ uint32_t smem_u32(const void* p) {
    uint32_t a;
    asm("{ .reg .u64 t; cvta.to.shared.u64 t, %1; cvt.u32.u64 %0, t; }" : "=r"(a) : "l"(p));
    return a;
}
__device__ __forceinline__ void cp16(uint32_t dst, const void* src) {
    asm volatile("cp.async.cg.shared.global [%0], [%1], 16;" :: "r"(dst), "l"(src));
}
#define CP_COMMIT() asm volatile("cp.async.commit_group;" ::: "memory")
#define CP_WAIT1()  asm volatile("cp.async.wait_group 1;" ::: "memory")

__device__ __forceinline__ void mma16816(float* c, const uint32_t* a, const uint32_t* b) {
    asm volatile("mma.sync.aligned.m16n8k16.row.col.f32.bf16.bf16.f32 "
        "{%0,%1,%2,%3}, {%4,%5,%6,%7}, {%8,%9}, {%0,%1,%2,%3};"
        : "+f"(c[0]), "+f"(c[1]), "+f"(c[2]), "+f"(c[3])
        : "r"(a[0]), "r"(a[1]), "r"(a[2]), "r"(a[3]), "r"(b[0]), "r"(b[1]));
}
__device__ __forceinline__ void ldA(uint32_t* a, const char* tile, int rm, int kk, int g, int q) {
    const char* p = tile + (rm + g) * STRIDE + (kk + q * 2) * 2;
    a[0] = *(const uint32_t*)p;
    a[1] = *(const uint32_t*)(p + 8 * STRIDE);
    a[2] = *(const uint32_t*)(p + 16);
    a[3] = *(const uint32_t*)(p + 8 * STRIDE + 16);
}
__device__ __forceinline__ void ldB(uint32_t* b, const char* tile, int cn, int kk, int g, int q) {
    const char* p = tile + (cn + g) * STRIDE + (kk + q * 2) * 2;
    b[0] = *(const uint32_t*)p;
    b[1] = *(const uint32_t*)(p + 16);
}
__device__ __forceinline__ uint32_t b2u(__nv_bfloat162 v) { return *reinterpret_cast<uint32_t*>(&v); }

// split 8 fp32 (two float4) into 8 bf16 hi + 8 bf16 lo
__device__ __forceinline__ void cvt_pair(const float4 A, const float4 B, uint4& hi, uint4& lo) {
    __nv_bfloat162 h0 = __floats2bfloat162_rn(A.x, A.y);
    __nv_bfloat162 h1 = __floats2bfloat162_rn(A.z, A.w);
    __nv_bfloat162 h2 = __floats2bfloat162_rn(B.x, B.y);
    __nv_bfloat162 h3 = __floats2bfloat162_rn(B.z, B.w);
    __nv_bfloat162 l0 = __floats2bfloat162_rn(A.x - __bfloat162float(h0.x), A.y - __bfloat162float(h0.y));
    __nv_bfloat162 l1 = __floats2bfloat162_rn(A.z - __bfloat162float(h1.x), A.w - __bfloat162float(h1.y));
    __nv_bfloat162 l2 = __floats2bfloat162_rn(B.x - __bfloat162float(h2.x), B.y - __bfloat162float(h2.y));
    __nv_bfloat162 l3 = __floats2bfloat162_rn(B.z - __bfloat162float(h3.x), B.w - __bfloat162float(h3.y));
    hi = make_uint4(b2u(h0), b2u(h1), b2u(h2), b2u(h3));
    lo = make_uint4(b2u(l0), b2u(l1), b2u(l2), b2u(l3));
}

// ---------------- split fp32 -> bf16 hi/lo, 4-way strip-mined (MLP=8) ----------------
// q = number of 8-float groups per strip; total groups = 4*q. Grid covers q.
__global__ __launch_bounds__(256) void split4_kernel(const float4* __restrict__ src,
                                                     uint4* __restrict__ hi,
                                                     uint4* __restrict__ lo, int q) {
    int i = blockIdx.x * 256 + threadIdx.x;
    if (i >= q) return;
    // front-batch 8 independent LDG.128
    float4 a0 = src[2*(size_t)i],             b0 = src[2*(size_t)i + 1];
    float4 a1 = src[2*((size_t)i + q)],       b1 = src[2*((size_t)i + q) + 1];
    float4 a2 = src[2*((size_t)i + 2*q)],     b2 = src[2*((size_t)i + 2*q) + 1];
    float4 a3 = src[2*((size_t)i + 3*q)],     b3 = src[2*((size_t)i + 3*q) + 1];
    uint4 h, l;
    cvt_pair(a0, b0, h, l); hi[i]         = h; lo[i]         = l;
    cvt_pair(a1, b1, h, l); hi[i + q]     = h; lo[i + q]     = l;
    cvt_pair(a2, b2, h, l); hi[i + 2*q]   = h; lo[i + 2*q]   = l;
    cvt_pair(a3, b3, h, l); hi[i + 3*q]   = h; lo[i + 3*q]   = l;
}

// ---------------- gate / routing ----------------
__global__ void gate_kernel(const float* __restrict__ x, const float* __restrict__ Wg) {
    int t = blockIdx.x;
    int warp = threadIdx.x >> 5, lane = threadIdx.x & 31;
    __shared__ float logits[E];
    const float* xr = x + (size_t)t * D;
    const float* wr = Wg + (size_t)warp * D;
    float s = 0.f;
    #pragma unroll
    for (int j = 0; j < D / 128; j++) {
        int i = lane * 4 + j * 128;
        float4 xv = *(const float4*)(xr + i);
        float4 wv = *(const float4*)(wr + i);
        s += xv.x * wv.x + xv.y * wv.y + xv.z * wv.z + xv.w * wv.w;
    }
    #pragma unroll
    for (int o = 16; o; o >>= 1) s += __shfl_xor_sync(0xffffffffu, s, o);
    if (lane == 0) logits[warp] = s;
    __syncthreads();
    if (threadIdx.x == 0) {
        float m = logits[0];
        #pragma unroll
        for (int e2 = 1; e2 < E; e2++) m = fmaxf(m, logits[e2]);
        float p[E];
        #pragma unroll
        for (int e2 = 0; e2 < E; e2++) p[e2] = expf(logits[e2] - m);
        int i0 = 0;
        #pragma unroll
        for (int e2 = 1; e2 < E; e2++) if (p[e2] > p[i0]) i0 = e2;
        int i1 = (i0 == 0) ? 1 : 0;
        #pragma unroll
        for (int e2 = 0; e2 < E; e2++) if (e2 != i0 && p[e2] > p[i1]) i1 = e2;
        float inv = 1.f / (p[i0] + p[i1]);
        g_pidx[2*t]   = i0; g_pw[2*t]   = p[i0] * inv;
        g_pidx[2*t+1] = i1; g_pw[2*t+1] = p[i1] * inv;
    }
}

__global__ void build_lists_kernel() {
    int e = blockIdx.x, tid = threadIdx.x;
    int lane = tid & 31, warp = tid >> 5;
    __shared__ int warp_cnt[8];
    __shared__ int base_s;
    if (tid == 0) base_s = 0;
    __syncthreads();
    for (int c = 0; c < NPAIR; c += 256) {
        int i = c + tid;
        bool m = (g_pidx[i] == e);
        unsigned bal = __ballot_sync(0xffffffffu, m);
        if (lane == 0) warp_cnt[warp] = __popc(bal);
        __syncthreads();
        int pos = base_s;
        for (int w = 0; w < warp; w++) pos += warp_cnt[w];
        pos += __popc(bal & ((1u << lane) - 1u));
        if (m) { g_plist[e][pos] = i; g_wlist[e][pos] = g_pw[i]; }
        __syncthreads();
        if (tid == 0) {
            int tot = 0;
            #pragma unroll
            for (int w = 0; w < 8; w++) tot += warp_cnt[w];
            base_s += tot;
        }
        __syncthreads();
    }
    if (tid == 0) g_count[e] = base_s;
}

// ---------------- UP GEMM: h = silu(x W1^T) * (x W3^T), split-bf16 mma ----------------
// Stage layout (bytes): Ah 0, Al 18432, B1h 36864, B1l 46080, B3h 55296, B3l 64512
#define UP_STG 73728
#define UP_SMEM (1024 + 2*UP_STG)

__global__ __launch_bounds__(256, 1) void ffn_up_mma() {
    int e = blockIdx.z;
    int cnt = g_count[e];
    int m0 = blockIdx.x * BM;
    if (m0 >= cnt) return;
    int n0 = blockIdx.y * BN;

    extern __shared__ __align__(128) char smem[];
    int* ps = (int*)smem;
    int tid = threadIdx.x;
    if (tid < BM) { int s = m0 + tid; ps[tid] = (s < cnt) ? g_plist[e][s] : -1; }
    __syncthreads();

    char* tiles = smem + 1024;
    uint32_t tiles_u = smem_u32(tiles);
    const size_t wbase = (size_t)e * H * D + (size_t)n0 * D;
    const int NS = D / BK;  // 16

    auto issue = [&](int s) {
        uint32_t tb = tiles_u + (s & 1) * UP_STG;
        int k0 = s * BK;
        #pragma unroll
        for (int j = 0; j < 16; j++) {
            int idx = tid + j * 256;
            if (idx < 2048) {  // A: x rows gathered by pair
                int part = idx >> 10, rem = idx & 1023, r = rem >> 3, c = rem & 7;
                int pr = ps[r];
                int tok = (pr < 0) ? 0 : (pr >> 1);
                const __nv_bfloat16* src = (part ? g_xl : g_xh) + (size_t)tok * D + k0 + c * 8;
                cp16(tb + part * 18432 + r * STRIDE + c * 16, src);
            } else {           // B: W1 / W3 rows
                int idx2 = idx - 2048;
                int mat = idx2 >> 10, rem = idx2 & 1023, part = rem >> 9, r = (rem >> 3) & 63, c = rem & 7;
                const __nv_bfloat16* base = mat ? (part ? g_W3l : g_W3h) : (part ? g_W1l : g_W1h);
                cp16(tb + 36864 + mat * 18432 + part * 9216 + r * STRIDE + c * 16,
                     base + wbase + (size_t)r * D + k0 + c * 8);
            }
        }
    };

    int wid = tid >> 5, lane = tid & 31;
    int wm = wid & 3, wn = wid >> 2;
    int g = lane >> 2, q = lane & 3;

    float a1[2][4][4], a3[2][4][4];
    #pragma unroll
    for (int i = 0; i < 2; i++)
        #pragma unroll
        for (int j = 0; j < 4; j++)
            #pragma unroll
            for (int k = 0; k < 4; k++) { a1[i][j][k] = 0.f; a3[i][j][k] = 0.f; }

    issue(0); CP_COMMIT();
    issue(1); CP_COMMIT();

    for (int s = 0; s < NS; s++) {
        CP_WAIT1();
        __syncthreads();
        const char* tb = tiles + (s & 1) * UP_STG;
        const char* Ah = tb,           *Al  = tb + 18432;
        const char* B1h = tb + 36864,  *B1l = tb + 46080;
        const char* B3h = tb + 55296,  *B3l = tb + 64512;
        #pragma unroll
        for (int kk = 0; kk < BK; kk += 16) {
            uint32_t fAh[2][4], fAl[2][4];
            #pragma unroll
            for (int mi = 0; mi < 2; mi++) {
                ldA(fAh[mi], Ah, wm * 32 + mi * 16, kk, g, q);
                ldA(fAl[mi], Al, wm * 32 + mi * 16, kk, g, q);
            }
            {   // W1
                uint32_t bh[4][2], bl[4][2];
                #pragma unroll
                for (int nj = 0; nj < 4; nj++) {
                    ldB(bh[nj], B1h, wn * 32 + nj * 8, kk, g, q);
                    ldB(bl[nj], B1l, wn * 32 + nj * 8, kk, g, q);
                }
                #pragma unroll
                for (int mi = 0; mi < 2; mi++)
                    #pragma unroll
                    for (int nj = 0; nj < 4; nj++) {
                        mma16816(a1[mi][nj], fAh[mi], bh[nj]);
                        mma16816(a1[mi][nj], fAh[mi], bl[nj]);
                        mma16816(a1[mi][nj], fAl[mi], bh[nj]);
                    }
            }
            {   // W3
                uint32_t bh[4][2], bl[4][2];
                #pragma unroll
                for (int nj = 0; nj < 4; nj++) {
                    ldB(bh[nj], B3h, wn * 32 + nj * 8, kk, g, q);
                    ldB(bl[nj], B3l, wn * 32 + nj * 8, kk, g, q);
                }
                #pragma unroll
                for (int mi = 0; mi < 2; mi++)
                    #pragma unroll
                    for (int nj = 0; nj < 4; nj++) {
                        mma16816(a3[mi][nj], fAh[mi], bh[nj]);
                        mma16816(a3[mi][nj], fAh[mi], bl[nj]);
                        mma16816(a3[mi][nj], fAl[mi], bh[nj]);
                    }
            }
        }
        __syncthreads();
        if (s + 2 < NS) issue(s + 2);
        CP_COMMIT();
    }

    // epilogue: silu(z)*u, split to hi/lo, store bf16x2
    #pragma unroll
    for (int mi = 0; mi < 2; mi++) {
        #pragma unroll
        for (int nj = 0; nj < 4; nj++) {
            int lr0 = wm * 32 + mi * 16 + g, lr1 = lr0 + 8;
            int n = n0 + wn * 32 + nj * 8 + q * 2;
            float* c1 = a1[mi][nj];
            float* c3 = a3[mi][nj];
            #pragma unroll
            for (int half = 0; half < 2; half++) {
                int p = ps[half ? lr1 : lr0];
                if (p < 0) continue;
                float z0 = c1[half * 2], z1 = c1[half * 2 + 1];
                float u0 = c3[half * 2], u1 = c3[half * 2 + 1];
                float h0 = (z0 / (1.f + __expf(-z0))) * u0;
                float h1 = (z1 / (1.f + __expf(-z1))) * u1;
                __nv_bfloat162 hh = __floats2bfloat162_rn(h0, h1);
                __nv_bfloat162 ll = __floats2bfloat162_rn(h0 - __bfloat162float(hh.x),
                                                          h1 - __bfloat162float(hh.y));
                *(uint32_t*)(g_hh + (size_t)p * H + n) = b2u(hh);
                *(uint32_t*)(g_hl + (size_t)p * H + n) = b2u(ll);
            }
        }
    }
}

// ---------------- DOWN GEMM: yp = w * (h W2^T), split-bf16 mma ----------------
// Stage layout: Ah 0, Al 18432, Bh 36864, Bl 46080
#define DN_STG 55296
#define DN_SMEM (1024 + 2*DN_STG)

__global__ __launch_bounds__(256, 1) void ffn_down_mma() {
    int e = blockIdx.z;
    int cnt = g_count[e];
    int m0 = blockIdx.x * BM;
    if (m0 >= cnt) return;
    int n0 = blockIdx.y * BN;

    extern __shared__ __align__(128) char smem[];
    int* ps = (int*)smem;
    float* pwS = (float*)(smem + 512);
    int tid = threadIdx.x;
    if (tid < BM) {
        int s = m0 + tid;
        if (s < cnt) { ps[tid] = g_plist[e][s]; pwS[tid] = g_wlist[e][s]; }
        else         { ps[tid] = -1;            pwS[tid] = 0.f; }
    }
    __syncthreads();

    char* tiles = smem + 1024;
    uint32_t tiles_u = smem_u32(tiles);
    const size_t wbase = (size_t)e * D * H + (size_t)n0 * H;
    const int NS = H / BK;  // 44

    auto issue = [&](int s) {
        uint32_t tb = tiles_u + (s & 1) * DN_STG;
        int k0 = s * BK;
        #pragma unroll
        for (int j = 0; j < 12; j++) {
            int idx = tid + j * 256;
            if (idx < 2048) {  // A: h rows by pair
                int part = idx >> 10, rem = idx & 1023, r = rem >> 3, c = rem & 7;
                int p = ps[r];
                int pr = (p < 0) ? 0 : p;
                const __nv_bfloat16* src = (part ? g_hl : g_hh) + (size_t)pr * H + k0 + c * 8;
                cp16(tb + part * 18432 + r * STRIDE + c * 16, src);
            } else {           // B: W2 rows
                int idx2 = idx - 2048;
                int part = idx2 >> 9, r = (idx2 >> 3) & 63, c = idx2 & 7;
                const __nv_bfloat16* base = part ? g_W2l : g_W2h;
                cp16(tb + 36864 + part * 9216 + r * STRIDE + c * 16,
                     base + wbase + (size_t)r * H + k0 + c * 8);
            }
        }
    };

    int wid = tid >> 5, lane = tid & 31;
    int wm = wid & 3, wn = wid >> 2;
    int g = lane >> 2, q = lane & 3;

    float acc[2][4][4];
    #pragma unroll
    for (int i = 0; i < 2; i++)
        #pragma unroll
        for (int j = 0; j < 4; j++)
            #pragma unroll
            for (int k = 0; k < 4; k++) acc[i][j][k] = 0.f;

    issue(0); CP_COMMIT();
    issue(1); CP_COMMIT();

    for (int s = 0; s < NS; s++) {
        CP_WAIT1();
        __syncthreads();
        const char* tb = tiles + (s & 1) * DN_STG;
        const char* Ah = tb,          *Al = tb + 18432;
        const char* Bh = tb + 36864,  *Bl = tb + 46080;
        #pragma unroll
        for (int kk = 0; kk < BK; kk += 16) {
            uint32_t fAh[2][4], fAl[2][4];
            #pragma unroll
            for (int mi = 0; mi < 2; mi++) {
                ldA(fAh[mi], Ah, wm * 32 + mi * 16, kk, g, q);
                ldA(fAl[mi], Al, wm * 32 + mi * 16, kk, g, q);
            }
            uint32_t bh[4][2], bl[4][2];
            #pragma unroll
            for (int nj = 0; nj < 4; nj++) {
                ldB(bh[nj], Bh, wn * 32 + nj * 8, kk, g, q);
                ldB(bl[nj], Bl, wn * 32 + nj * 8, kk, g, q);
            }
            #pragma unroll
            for (int mi = 0; mi < 2; mi++)
                #pragma unroll
                for (int nj = 0; nj < 4; nj++) {
                    mma16816(acc[mi][nj], fAh[mi], bh[nj]);
                    mma16816(acc[mi][nj], fAh[mi], bl[nj]);
                    mma16816(acc[mi][nj], fAl[mi], bh[nj]);
                }
        }
        __syncthreads();
        if (s + 2 < NS) issue(s + 2);
        CP_COMMIT();
    }

    #pragma unroll
    for (int mi = 0; mi < 2; mi++) {
        #pragma unroll
        for (int nj = 0; nj < 4; nj++) {
            int lr0 = wm * 32 + mi * 16 + g, lr1 = lr0 + 8;
            int n = n0 + wn * 32 + nj * 8 + q * 2;
            float* c = acc[mi][nj];
            #pragma unroll
            for (int half = 0; half < 2; half++) {
                int lr = half ? lr1 : lr0;
                int p = ps[lr];
                if (p < 0) continue;
                float w = pwS[lr];
                float2 v = make_float2(w * c[half * 2], w * c[half * 2 + 1]);
                *(float2*)(g_yp + (size_t)p * D + n) = v;
            }
        }
    }
}

// ---------------- combine ----------------
__global__ void combine_kernel(float* __restrict__ y) {
    int i = blockIdx.x * 256 + threadIdx.x;
    int t = i / D, d = i - t * D;
    y[i] = g_yp[(size_t)(2 * t) * D + d] + g_yp[(size_t)(2 * t + 1) * D + d];
}

// ---------------- launch ----------------
extern "C" void kernel_launch(void* const* d_in, const int* in_sizes, int n_in,
                              void* d_out, int out_size) {
    const float* x  = (const float*)d_in[0];
    const float* Wg = (const float*)d_in[1];
    const float* W1 = (const float*)d_in[2];
    const float* W2 = (const float*)d_in[3];
    const float* W3 = (const float*)d_in[4];
    float* y = (float*)d_out;

    cudaFuncSetAttribute(ffn_up_mma,   cudaFuncAttributeMaxDynamicSharedMemorySize, UP_SMEM);
    cudaFuncSetAttribute(ffn_down_mma, cudaFuncAttributeMaxDynamicSharedMemorySize, DN_SMEM);

    // pre-split fp32 -> bf16 hi/lo (4-way strip-mined, MLP=8)
    {
        int qW = (int)((size_t)E * H * D / 8 / 4);   // 720,896 groups per strip
        int qX = T * D / 8 / 4;                      // 65,536
        __nv_bfloat16 *w1h, *w1l, *w3h, *w3l, *w2h, *w2l, *xh, *xl;
        cudaGetSymbolAddress((void**)&w1h, g_W1h); cudaGetSymbolAddress((void**)&w1l, g_W1l);
        cudaGetSymbolAddress((void**)&w3h, g_W3h); cudaGetSymbolAddress((void**)&w3l, g_W3l);
        cudaGetSymbolAddress((void**)&w2h, g_W2h); cudaGetSymbolAddress((void**)&w2l, g_W2l);
        cudaGetSymbolAddress((void**)&xh,  g_xh);  cudaGetSymbolAddress((void**)&xl,  g_xl);
        split4_kernel<<<(qW + 255) / 256, 256>>>((const float4*)W1, (uint4*)w1h, (uint4*)w1l, qW);
        split4_kernel<<<(qW + 255) / 256, 256>>>((const float4*)W3, (uint4*)w3h, (uint4*)w3l, qW);
        split4_kernel<<<(qW + 255) / 256, 256>>>((const float4*)W2, (uint4*)w2h, (uint4*)w2l, qW);
        split4_kernel<<<(qX + 255) / 256, 256>>>((const float4*)x,  (uint4*)xh,  (uint4*)xl,  qX);
    }

    gate_kernel<<<T, 256>>>(x, Wg);
    build_lists_kernel<<<E, 256>>>();

    dim3 g1(T / BM, H / BN, E);   // 16 x 44 x 8
    ffn_up_mma<<<g1, 256, UP_SMEM>>>();

    dim3 g2(T / BM, D / BN, E);   // 16 x 16 x 8
    ffn_down_mma<<<g2, 256, DN_SMEM>>>();

    combine_kernel<<<(T * D) / 256, 256>>>(y);
}

// round 7
// speedup vs baseline: 1.1751x; 1.0125x over previous
#include <cuda_runtime.h>
#include <cuda_bf16.h>
#include <cstdint>
#include <math.h>

#define T 2048      // tokens
#define D 1024      // model dim
#define H 2816      // ffn hidden
#define E 8         // experts
#define NPAIR (T*2) // token-expert pairs

#define BM 128
#define BN 64
#define BK 32
#define STRIDE 80   // padded bytes per k-row: 32*2 + 16 (bank-conflict-free: 20g+q distinct)

// ---------------- device globals (no allocation allowed) ----------------
__device__ int   g_pidx[NPAIR];
__device__ float g_pw[NPAIR];
__device__ int   g_count[E];
__device__ int   g_plist[E][T];
__device__ float g_wlist[E][T];

__device__ __align__(16) __nv_bfloat16 g_xh[T*D],  g_xl[T*D];
__device__ __align__(16) __nv_bfloat16 g_W1h[(size_t)E*H*D], g_W1l[(size_t)E*H*D];
__device__ __align__(16) __nv_bfloat16 g_W3h[(size_t)E*H*D], g_W3l[(size_t)E*H*D];
__device__ __align__(16) __nv_bfloat16 g_W2h[(size_t)E*D*H], g_W2l[(size_t)E*D*H];
__device__ __align__(16) __nv_bfloat16 g_hh[(size_t)NPAIR*H], g_hl[(size_t)NPAIR*H];
__device__ float g_yp[(size_t)NPAIR*D];

// ---------------- helpers ----------------
__device__ __forceinline__ uint32_t smem_u32(const void* p) {
    uint32_t a;
    asm("{ .reg .u64 t; cvta.to.shared.u64 t, %1; cvt.u32.u64 %0, t; }" : "=r"(a) : "l"(p));
    return a;
}
__device__ __forceinline__ void cp16(uint32_t dst, const void* src) {
    asm volatile("cp.async.cg.shared.global [%0], [%1], 16;" :: "r"(dst), "l"(src));
}
#define CP_COMMIT() asm volatile("cp.async.commit_group;" ::: "memory")
#define CP_WAIT1()  asm volatile("cp.async.wait_group 1;" ::: "memory")

__device__ __forceinline__ void mma16816(float* c, const uint32_t* a, const uint32_t* b) {
    asm volatile("mma.sync.aligned.m16n8k16.row.col.f32.bf16.bf16.f32 "
        "{%0,%1,%2,%3}, {%4,%5,%6,%7}, {%8,%9}, {%0,%1,%2,%3};"
        : "+f"(c[0]), "+f"(c[1]), "+f"(c[2]), "+f"(c[3])
        : "r"(a[0]), "r"(a[1]), "r"(a[2]), "r"(a[3]), "r"(b[0]), "r"(b[1]));
}
__device__ __forceinline__ void ldA(uint32_t* a, const char* tile, int rm, int kk, int g, int q) {
    const char* p = tile + (rm + g) * STRIDE + (kk + q * 2) * 2;
    a[0] = *(const uint32_t*)p;
    a[1] = *(const uint32_t*)(p + 8 * STRIDE);
    a[2] = *(const uint32_t*)(p + 16);
    a[3] = *(const uint32_t*)(p + 8 * STRIDE + 16);
}
__device__ __forceinline__ void ldB(uint32_t* b, const char* tile, int cn, int kk, int g, int q) {
    const char* p = tile + (cn + g) * STRIDE + (kk + q * 2) * 2;
    b[0] = *(const uint32_t*)p;
    b[1] = *(const uint32_t*)(p + 16);
}
__device__ __forceinline__ uint32_t b2u(__nv_bfloat162 v) { return *reinterpret_cast<uint32_t*>(&v); }

// split 8 fp32 (two float4) into 8 bf16 hi + 8 bf16 lo
__device__ __forceinline__ void cvt_pair(const float4 A, const float4 B, uint4& hi, uint4& lo) {
    __nv_bfloat162 h0 = __floats2bfloat162_rn(A.x, A.y);
    __nv_bfloat162 h1 = __floats2bfloat162_rn(A.z, A.w);
    __nv_bfloat162 h2 = __floats2bfloat162_rn(B.x, B.y);
    __nv_bfloat162 h3 = __floats2bfloat162_rn(B.z, B.w);
    __nv_bfloat162 l0 = __floats2bfloat162_rn(A.x - __bfloat162float(h0.x), A.y - __bfloat162float(h0.y));
    __nv_bfloat162 l1 = __floats2bfloat162_rn(A.z - __bfloat162float(h1.x), A.w - __bfloat162float(h1.y));
    __nv_bfloat162 l2 = __floats2bfloat162_rn(B.x - __bfloat162float(h2.x), B.y - __bfloat162float(h2.y));
    __nv_bfloat162 l3 = __floats2bfloat162_rn(B.z - __bfloat162float(h3.x), B.w - __bfloat162float(h3.y));
    hi = make_uint4(b2u(h0), b2u(h1), b2u(h2), b2u(h3));
    lo = make_uint4(b2u(l0), b2u(l1), b2u(l2), b2u(l3));
}

// ---------------- split fp32 -> bf16 hi/lo, 4-way strip-mined ----------------
__global__ __launch_bounds__(256) void split4_kernel(const float4* __restrict__ src,
                                                     uint4* __restrict__ hi,
                                                     uint4* __restrict__ lo, int q) {
    int i = blockIdx.x * 256 + threadIdx.x;
    if (i >= q) return;
    float4 a0 = src[2*(size_t)i],             b0 = src[2*(size_t)i + 1];
    float4 a1 = src[2*((size_t)i + q)],       b1 = src[2*((size_t)i + q) + 1];
    float4 a2 = src[2*((size_t)i + 2*q)],     b2 = src[2*((size_t)i + 2*q) + 1];
    float4 a3 = src[2*((size_t)i + 3*q)],     b3 = src[2*((size_t)i + 3*q) + 1];
    uint4 h, l;
    cvt_pair(a0, b0, h, l); hi[i]         = h; lo[i]         = l;
    cvt_pair(a1, b1, h, l); hi[i + q]     = h; lo[i + q]     = l;
    cvt_pair(a2, b2, h, l); hi[i + 2*q]   = h; lo[i + 2*q]   = l;
    cvt_pair(a3, b3, h, l); hi[i + 3*q]   = h; lo[i + 3*q]   = l;
}

// ---------------- gate / routing ----------------
__global__ void gate_kernel(const float* __restrict__ x, const float* __restrict__ Wg) {
    int t = blockIdx.x;
    int warp = threadIdx.x >> 5, lane = threadIdx.x & 31;
    __shared__ float logits[E];
    const float* xr = x + (size_t)t * D;
    const float* wr = Wg + (size_t)warp * D;
    float s = 0.f;
    #pragma unroll
    for (int j = 0; j < D / 128; j++) {
        int i = lane * 4 + j * 128;
        float4 xv = *(const float4*)(xr + i);
        float4 wv = *(const float4*)(wr + i);
        s += xv.x * wv.x + xv.y * wv.y + xv.z * wv.z + xv.w * wv.w;
    }
    #pragma unroll
    for (int o = 16; o; o >>= 1) s += __shfl_xor_sync(0xffffffffu, s, o);
    if (lane == 0) logits[warp] = s;
    __syncthreads();
    if (threadIdx.x == 0) {
        float m = logits[0];
        #pragma unroll
        for (int e2 = 1; e2 < E; e2++) m = fmaxf(m, logits[e2]);
        float p[E];
        #pragma unroll
        for (int e2 = 0; e2 < E; e2++) p[e2] = expf(logits[e2] - m);
        int i0 = 0;
        #pragma unroll
        for (int e2 = 1; e2 < E; e2++) if (p[e2] > p[i0]) i0 = e2;
        int i1 = (i0 == 0) ? 1 : 0;
        #pragma unroll
        for (int e2 = 0; e2 < E; e2++) if (e2 != i0 && p[e2] > p[i1]) i1 = e2;
        float inv = 1.f / (p[i0] + p[i1]);
        g_pidx[2*t]   = i0; g_pw[2*t]   = p[i0] * inv;
        g_pidx[2*t+1] = i1; g_pw[2*t+1] = p[i1] * inv;
    }
}

__global__ void build_lists_kernel() {
    int e = blockIdx.x, tid = threadIdx.x;
    int lane = tid & 31, warp = tid >> 5;
    __shared__ int warp_cnt[8];
    __shared__ int base_s;
    if (tid == 0) base_s = 0;
    __syncthreads();
    for (int c = 0; c < NPAIR; c += 256) {
        int i = c + tid;
        bool m = (g_pidx[i] == e);
        unsigned bal = __ballot_sync(0xffffffffu, m);
        if (lane == 0) warp_cnt[warp] = __popc(bal);
        __syncthreads();
        int pos = base_s;
        for (int w = 0; w < warp; w++) pos += warp_cnt[w];
        pos += __popc(bal & ((1u << lane) - 1u));
        if (m) { g_plist[e][pos] = i; g_wlist[e][pos] = g_pw[i]; }
        __syncthreads();
        if (tid == 0) {
            int tot = 0;
            #pragma unroll
            for (int w = 0; w < 8; w++) tot += warp_cnt[w];
            base_s += tot;
        }
        __syncthreads();
    }
    if (tid == 0) g_count[e] = base_s;
}

// ---------------- UP GEMM: h = silu(x W1^T) * (x W3^T), split-bf16 mma ----------------
// Stage (40960 B): Ah 0, Al 10240, B1h 20480, B1l 25600, B3h 30720, B3l 35840
#define UP_STG 40960
#define UP_SMEM (1024 + 2*UP_STG)

__global__ __launch_bounds__(256, 2) void ffn_up_mma() {
    int e = blockIdx.z;
    int cnt = g_count[e];
    int m0 = blockIdx.x * BM;
    if (m0 >= cnt) return;
    int n0 = blockIdx.y * BN;

    extern __shared__ __align__(128) char smem[];
    int* ps = (int*)smem;
    int tid = threadIdx.x;
    if (tid < BM) { int s = m0 + tid; ps[tid] = (s < cnt) ? g_plist[e][s] : -1; }
    __syncthreads();

    char* tiles = smem + 1024;
    uint32_t tiles_u = smem_u32(tiles);
    const size_t wbase = (size_t)e * H * D + (size_t)n0 * D;
    const int NS = D / BK;  // 32

    auto issue = [&](int s) {
        uint32_t tb = tiles_u + (s & 1) * UP_STG;
        int k0 = s * BK;
        #pragma unroll
        for (int j = 0; j < 8; j++) {
            int idx = tid + j * 256;
            if (idx < 1024) {  // A: x rows gathered by pair (hi/lo)
                int part = idx >> 9, rem = idx & 511, r = rem >> 2, c = rem & 3;
                int pr = ps[r];
                int tok = (pr < 0) ? 0 : (pr >> 1);
                const __nv_bfloat16* src = (part ? g_xl : g_xh) + (size_t)tok * D + k0 + c * 8;
                cp16(tb + part * 10240 + r * STRIDE + c * 16, src);
            } else {           // B: W1 / W3 rows (hi/lo)
                int idx2 = idx - 1024;
                int mat = idx2 >> 9, rem = idx2 & 511, part = rem >> 8, r = (rem >> 2) & 63, c = rem & 3;
                const __nv_bfloat16* base = mat ? (part ? g_W3l : g_W3h) : (part ? g_W1l : g_W1h);
                cp16(tb + 20480 + mat * 10240 + part * 5120 + r * STRIDE + c * 16,
                     base + wbase + (size_t)r * D + k0 + c * 8);
            }
        }
    };

    int wid = tid >> 5, lane = tid & 31;
    int wm = wid & 3, wn = wid >> 2;
    int g = lane >> 2, q = lane & 3;

    float a1[2][4][4], a3[2][4][4];
    #pragma unroll
    for (int i = 0; i < 2; i++)
        #pragma unroll
        for (int j = 0; j < 4; j++)
            #pragma unroll
            for (int k = 0; k < 4; k++) { a1[i][j][k] = 0.f; a3[i][j][k] = 0.f; }

    issue(0); CP_COMMIT();
    issue(1); CP_COMMIT();

    for (int s = 0; s < NS; s++) {
        CP_WAIT1();
        __syncthreads();
        const char* tb = tiles + (s & 1) * UP_STG;
        const char* Ah = tb,           *Al  = tb + 10240;
        const char* B1h = tb + 20480,  *B1l = tb + 25600;
        const char* B3h = tb + 30720,  *B3l = tb + 35840;
        #pragma unroll
        for (int kk = 0; kk < BK; kk += 16) {
            uint32_t fAh[2][4], fAl[2][4];
            #pragma unroll
            for (int mi = 0; mi < 2; mi++) {
                ldA(fAh[mi], Ah, wm * 32 + mi * 16, kk, g, q);
                ldA(fAl[mi], Al, wm * 32 + mi * 16, kk, g, q);
            }
            {   // W1
                uint32_t bh[4][2], bl[4][2];
                #pragma unroll
                for (int nj = 0; nj < 4; nj++) {
                    ldB(bh[nj], B1h, wn * 32 + nj * 8, kk, g, q);
                    ldB(bl[nj], B1l, wn * 32 + nj * 8, kk, g, q);
                }
                #pragma unroll
                for (int mi = 0; mi < 2; mi++)
                    #pragma unroll
                    for (int nj = 0; nj < 4; nj++) {
                        mma16816(a1[mi][nj], fAh[mi], bh[nj]);
                        mma16816(a1[mi][nj], fAh[mi], bl[nj]);
                        mma16816(a1[mi][nj], fAl[mi], bh[nj]);
                    }
            }
            {   // W3
                uint32_t bh[4][2], bl[4][2];
                #pragma unroll
                for (int nj = 0; nj < 4; nj++) {
                    ldB(bh[nj], B3h, wn * 32 + nj * 8, kk, g, q);
                    ldB(bl[nj], B3l, wn * 32 + nj * 8, kk, g, q);
                }
                #pragma unroll
                for (int mi = 0; mi < 2; mi++)
                    #pragma unroll
                    for (int nj = 0; nj < 4; nj++) {
                        mma16816(a3[mi][nj], fAh[mi], bh[nj]);
                        mma16816(a3[mi][nj], fAh[mi], bl[nj]);
                        mma16816(a3[mi][nj], fAl[mi], bh[nj]);
                    }
            }
        }
        __syncthreads();
        if (s + 2 < NS) issue(s + 2);
        CP_COMMIT();
    }

    // epilogue: silu(z)*u, split to hi/lo, store bf16x2
    #pragma unroll
    for (int mi = 0; mi < 2; mi++) {
        #pragma unroll
        for (int nj = 0; nj < 4; nj++) {
            int lr0 = wm * 32 + mi * 16 + g, lr1 = lr0 + 8;
            int n = n0 + wn * 32 + nj * 8 + q * 2;
            float* c1 = a1[mi][nj];
            float* c3 = a3[mi][nj];
            #pragma unroll
            for (int half = 0; half < 2; half++) {
                int p = ps[half ? lr1 : lr0];
                if (p < 0) continue;
                float z0 = c1[half * 2], z1 = c1[half * 2 + 1];
                float u0 = c3[half * 2], u1 = c3[half * 2 + 1];
                float h0 = (z0 / (1.f + __expf(-z0))) * u0;
                float h1 = (z1 / (1.f + __expf(-z1))) * u1;
                __nv_bfloat162 hh = __floats2bfloat162_rn(h0, h1);
                __nv_bfloat162 ll = __floats2bfloat162_rn(h0 - __bfloat162float(hh.x),
                                                          h1 - __bfloat162float(hh.y));
                *(uint32_t*)(g_hh + (size_t)p * H + n) = b2u(hh);
                *(uint32_t*)(g_hl + (size_t)p * H + n) = b2u(ll);
            }
        }
    }
}

// ---------------- DOWN GEMM: yp = w * (h W2^T), split-bf16 mma ----------------
// Stage (30720 B): Ah 0, Al 10240, Bh 20480, Bl 25600
#define DN_STG 30720
#define DN_SMEM (1024 + 2*DN_STG)

__global__ __launch_bounds__(256, 2) void ffn_down_mma() {
    int e = blockIdx.z;
    int cnt = g_count[e];
    int m0 = blockIdx.x * BM;
    if (m0 >= cnt) return;
    int n0 = blockIdx.y * BN;

    extern __shared__ __align__(128) char smem[];
    int* ps = (int*)smem;
    float* pwS = (float*)(smem + 512);
    int tid = threadIdx.x;
    if (tid < BM) {
        int s = m0 + tid;
        if (s < cnt) { ps[tid] = g_plist[e][s]; pwS[tid] = g_wlist[e][s]; }
        else         { ps[tid] = -1;            pwS[tid] = 0.f; }
    }
    __syncthreads();

    char* tiles = smem + 1024;
    uint32_t tiles_u = smem_u32(tiles);
    const size_t wbase = (size_t)e * D * H + (size_t)n0 * H;
    const int NS = H / BK;  // 88

    auto issue = [&](int s) {
        uint32_t tb = tiles_u + (s & 1) * DN_STG;
        int k0 = s * BK;
        #pragma unroll
        for (int j = 0; j < 6; j++) {
            int idx = tid + j * 256;
            if (idx < 1024) {  // A: h rows by pair (hi/lo)
                int part = idx >> 9, rem = idx & 511, r = rem >> 2, c = rem & 3;
                int p = ps[r];
                int pr = (p < 0) ? 0 : p;
                const __nv_bfloat16* src = (part ? g_hl : g_hh) + (size_t)pr * H + k0 + c * 8;
                cp16(tb + part * 10240 + r * STRIDE + c * 16, src);
            } else {           // B: W2 rows (hi/lo)
                int idx2 = idx - 1024;
                int part = idx2 >> 8, r = (idx2 >> 2) & 63, c = idx2 & 3;
                const __nv_bfloat16* base = part ? g_W2l : g_W2h;
                cp16(tb + 20480 + part * 5120 + r * STRIDE + c * 16,
                     base + wbase + (size_t)r * H + k0 + c * 8);
            }
        }
    };

    int wid = tid >> 5, lane = tid & 31;
    int wm = wid & 3, wn = wid >> 2;
    int g = lane >> 2, q = lane & 3;

    float acc[2][4][4];
    #pragma unroll
    for (int i = 0; i < 2; i++)
        #pragma unroll
        for (int j = 0; j < 4; j++)
            #pragma unroll
            for (int k = 0; k < 4; k++) acc[i][j][k] = 0.f;

    issue(0); CP_COMMIT();
    issue(1); CP_COMMIT();

    for (int s = 0; s < NS; s++) {
        CP_WAIT1();
        __syncthreads();
        const char* tb = tiles + (s & 1) * DN_STG;
        const char* Ah = tb,          *Al = tb + 10240;
        const char* Bh = tb + 20480,  *Bl = tb + 25600;
        #pragma unroll
        for (int kk = 0; kk < BK; kk += 16) {
            uint32_t fAh[2][4], fAl[2][4];
            #pragma unroll
            for (int mi = 0; mi < 2; mi++) {
                ldA(fAh[mi], Ah, wm * 32 + mi * 16, kk, g, q);
                ldA(fAl[mi], Al, wm * 32 + mi * 16, kk, g, q);
            }
            uint32_t bh[4][2], bl[4][2];
            #pragma unroll
            for (int nj = 0; nj < 4; nj++) {
                ldB(bh[nj], Bh, wn * 32 + nj * 8, kk, g, q);
                ldB(bl[nj], Bl, wn * 32 + nj * 8, kk, g, q);
            }
            #pragma unroll
            for (int mi = 0; mi < 2; mi++)
                #pragma unroll
                for (int nj = 0; nj < 4; nj++) {
                    mma16816(acc[mi][nj], fAh[mi], bh[nj]);
                    mma16816(acc[mi][nj], fAh[mi], bl[nj]);
                    mma16816(acc[mi][nj], fAl[mi], bh[nj]);
                }
        }
        __syncthreads();
        if (s + 2 < NS) issue(s + 2);
        CP_COMMIT();
    }

    #pragma unroll
    for (int mi = 0; mi < 2; mi++) {
        #pragma unroll
        for (int nj = 0; nj < 4; nj++) {
            int lr0 = wm * 32 + mi * 16 + g, lr1 = lr0 + 8;
            int n = n0 + wn * 32 + nj * 8 + q * 2;
            float* c = acc[mi][nj];
            #pragma unroll
            for (int half = 0; half < 2; half++) {
                int lr = half ? lr1 : lr0;
                int p = ps[lr];
                if (p < 0) continue;
                float w = pwS[lr];
                float2 v = make_float2(w * c[half * 2], w * c[half * 2 + 1]);
                *(float2*)(g_yp + (size_t)p * D + n) = v;
            }
        }
    }
}

// ---------------- combine ----------------
__global__ void combine_kernel(float* __restrict__ y) {
    int i = blockIdx.x * 256 + threadIdx.x;
    int t = i / D, d = i - t * D;
    y[i] = g_yp[(size_t)(2 * t) * D + d] + g_yp[(size_t)(2 * t + 1) * D + d];
}

// ---------------- launch ----------------
extern "C" void kernel_launch(void* const* d_in, const int* in_sizes, int n_in,
                              void* d_out, int out_size) {
    const float* x  = (const float*)d_in[0];
    const float* Wg = (const float*)d_in[1];
    const float* W1 = (const float*)d_in[2];
    const float* W2 = (const float*)d_in[3];
    const float* W3 = (const float*)d_in[4];
    float* y = (float*)d_out;

    cudaFuncSetAttribute(ffn_up_mma,   cudaFuncAttributeMaxDynamicSharedMemorySize, UP_SMEM);
    cudaFuncSetAttribute(ffn_down_mma, cudaFuncAttributeMaxDynamicSharedMemorySize, DN_SMEM);

    // pre-split fp32 -> bf16 hi/lo
    {
        int qW = (int)((size_t)E * H * D / 8 / 4);
        int qX = T * D / 8 / 4;
        __nv_bfloat16 *w1h, *w1l, *w3h, *w3l, *w2h, *w2l, *xh, *xl;
        cudaGetSymbolAddress((void**)&w1h, g_W1h); cudaGetSymbolAddress((void**)&w1l, g_W1l);
        cudaGetSymbolAddress((void**)&w3h, g_W3h); cudaGetSymbolAddress((void**)&w3l, g_W3l);
        cudaGetSymbolAddress((void**)&w2h, g_W2h); cudaGetSymbolAddress((void**)&w2l, g_W2l);
        cudaGetSymbolAddress((void**)&xh,  g_xh);  cudaGetSymbolAddress((void**)&xl,  g_xl);
        split4_kernel<<<(qW + 255) / 256, 256>>>((const float4*)W1, (uint4*)w1h, (uint4*)w1l, qW);
        split4_kernel<<<(qW + 255) / 256, 256>>>((const float4*)W3, (uint4*)w3h, (uint4*)w3l, qW);
        split4_kernel<<<(qW + 255) / 256, 256>>>((const float4*)W2, (uint4*)w2h, (uint4*)w2l, qW);
        split4_kernel<<<(qX + 255) / 256, 256>>>((const float4*)x,  (uint4*)xh,  (uint4*)xl,  qX);
    }

    gate_kernel<<<T, 256>>>(x, Wg);
    build_lists_kernel<<<E, 256>>>();

    dim3 g1(T / BM, H / BN, E);   // 16 x 44 x 8
    ffn_up_mma<<<g1, 256, UP_SMEM>>>();

    dim3 g2(T / BM, D / BN, E);   // 16 x 16 x 8
    ffn_down_mma<<<g2, 256, DN_SMEM>>>();

    combine_kernel<<<(T * D) / 256, 256>>>(y);
}